// round 12
// baseline (speedup 1.0000x reference)
#include <cuda_runtime.h>
#include <math.h>

#define S_ 8192
#define D_ 64
#define N_ 2048
#define O_ 8
#define GATHER_BLOCKS 256                 // 256 x 256 thr = 65536 = S_*O_
#define LSE_BLOCKS (2 * N_ + O_ + N_ / 8) // 4360

// ---- scratch (allocation-free rule: __device__ globals) ----
__device__ float d_lse0[N_];
__device__ float d_lse1[N_];
__device__ float d_lse2[N_];
__device__ float d_lse_out[O_];
__device__ uint4 d_walk[S_ * O_];   // {bits(w_out+w2+w1), r2, r1, r0}

// ---------------------------------------------------------------------------
// Kernel A: R7 structure, proven 5.67us: 3-round index walk (hides under the
// LSE MUFU floor) + row-wise logsumexp tables. Adds griddepcontrol.
// launch_dependents at entry so the PDL-launched kernel B spawns while A is
// still running (B's launch overhead + x staging overlap A).
// ---------------------------------------------------------------------------
__global__ void __launch_bounds__(256) lse_gather_kernel(const float* __restrict__ w0,
                                                         const float* __restrict__ w1,
                                                         const float* __restrict__ w2,
                                                         const float* __restrict__ w_out,
                                                         const int* __restrict__ c1,
                                                         const int* __restrict__ c2,
                                                         const int* __restrict__ keys_out)
{
    asm volatile("griddepcontrol.launch_dependents;");

    __shared__ float smax[8];
    __shared__ float ssum[8];

    const int b = blockIdx.x;
    const int t = threadIdx.x;
    const int lane = t & 31;
    const int warp = t >> 5;

    if (b < GATHER_BLOCKS) {
        // ========== index walk: rounds 0-2 (hide fully under LSE) ==========
        const int tid = b * 256 + t;
        const int s = tid >> 3;          // / O_
        const int o = tid & 7;           // % O_

        const int r2 = keys_out[tid];                       // coalesced
        float logp = w_out[o * N_ + r2];

        const int r1 = c2[(size_t)s * N_ + r2];
        logp += w2[(size_t)r2 * N_ + r1];

        const int r0 = c1[(size_t)s * N_ + r1];
        logp += w1[(size_t)r1 * N_ + r0];

        d_walk[tid] = make_uint4(__float_as_uint(logp),
                                 (unsigned)r2, (unsigned)r1, (unsigned)r0);
        return;
    }

    const int b2 = b - GATHER_BLOCKS;
    if (b2 < 2 * N_ + O_) {
        // ================= wide rows: 2048 elements =================
        const float* row;
        float* dst;
        if (b2 < N_)          { row = w1    + (size_t)b2 * N_;           dst = &d_lse1[b2]; }
        else if (b2 < 2 * N_) { row = w2    + (size_t)(b2 - N_) * N_;    dst = &d_lse2[b2 - N_]; }
        else                  { row = w_out + (size_t)(b2 - 2*N_) * N_;  dst = &d_lse_out[b2 - 2*N_]; }

        const float4* row4 = (const float4*)row;
        float4 a = row4[t];
        float4 c = row4[t + 256];
        float v[8] = {a.x, a.y, a.z, a.w, c.x, c.y, c.z, c.w};

        float m = v[0];
        #pragma unroll
        for (int i = 1; i < 8; i++) m = fmaxf(m, v[i]);
        #pragma unroll
        for (int off = 16; off; off >>= 1) m = fmaxf(m, __shfl_xor_sync(0xffffffffu, m, off));
        if (lane == 0) smax[warp] = m;
        __syncthreads();
        float bm = smax[0];
        #pragma unroll
        for (int i = 1; i < 8; i++) bm = fmaxf(bm, smax[i]);

        float ss = 0.0f;
        #pragma unroll
        for (int i = 0; i < 8; i++) ss += __expf(v[i] - bm);
        #pragma unroll
        for (int off = 16; off; off >>= 1) ss += __shfl_xor_sync(0xffffffffu, ss, off);
        if (lane == 0) ssum[warp] = ss;
        __syncthreads();
        if (t == 0) {
            float tot = 0.0f;
            #pragma unroll
            for (int i = 0; i < 8; i++) tot += ssum[i];
            *dst = bm + __logf(tot);
        }
    } else {
        // ================= w0: 64-wide rows, one warp per row =================
        const int r = (b2 - (2 * N_ + O_)) * 8 + warp;
        const float* row = w0 + (size_t)r * D_;
        float v0 = row[lane];
        float v1 = row[lane + 32];
        float m = fmaxf(v0, v1);
        #pragma unroll
        for (int off = 16; off; off >>= 1) m = fmaxf(m, __shfl_xor_sync(0xffffffffu, m, off));
        float ss = __expf(v0 - m) + __expf(v1 - m);
        #pragma unroll
        for (int off = 16; off; off >>= 1) ss += __shfl_xor_sync(0xffffffffu, ss, off);
        if (lane == 0) d_lse0[r] = m + __logf(ss);
    }
}

// ---------------------------------------------------------------------------
// Kernel B (PDL): launched with programmatic-stream-serialization, so it
// starts DURING A. Pre-wait: stage this block's 32 x-rows (8KB, coalesced)
// into smem — removes the divergent x round entirely. Then griddepcontrol.wait
// (releases when A fully completes), then the short dependent chain:
// wlk(L2) -> c0 (the one DRAM round) -> w0(L2) + smem tables -> outputs.
// ---------------------------------------------------------------------------
__global__ void __launch_bounds__(256) finalize_kernel(const float* __restrict__ x,
                                                       const float* __restrict__ w0,
                                                       const int* __restrict__ c0,
                                                       float* __restrict__ out)
{
    __shared__ float s_x[32 * D_];      // 8 KB: 32 samples x 64 features
    __shared__ float s_lse0[N_];
    __shared__ float s_lse1[N_];
    __shared__ float s_lse2[N_];
    __shared__ float s_lse_out[O_];

    const int t = threadIdx.x;
    const int s0 = blockIdx.x * 32;     // first sample of this block

    // ---- pre-wait: inputs only (x is ready before A) ----
    const float4* x4 = (const float4*)(x + (size_t)s0 * D_);
    #pragma unroll
    for (int i = 0; i < 2; i++)         // 512 float4 per block
        ((float4*)s_x)[t + i * 256] = x4[t + i * 256];

    asm volatile("griddepcontrol.wait;");

    const int tid = blockIdx.x * blockDim.x + t;
    const int s = tid >> 3;             // / O_
    const int o = tid & 7;              // % O_

    // dependent chain first
    const uint4 wlk = d_walk[tid];                    // L2 (written by A)
    const int r2 = (int)wlk.y, r1 = (int)wlk.z, r0 = (int)wlk.w;
    const int cin = c0[(size_t)s * N_ + r0];          // the one DRAM round
    const float w0v = w0[r0 * D_ + cin];              // L2 (A's LSE pass)

    // table staging overlaps the chain (independent, coalesced from L2)
    const float4* g0 = (const float4*)d_lse0;
    const float4* g1 = (const float4*)d_lse1;
    const float4* g2 = (const float4*)d_lse2;
    #pragma unroll
    for (int i = 0; i < N_ / 4 / 256; i++) {          // 2 iters
        ((float4*)s_lse0)[t + i * 256] = g0[t + i * 256];
        ((float4*)s_lse1)[t + i * 256] = g1[t + i * 256];
        ((float4*)s_lse2)[t + i * 256] = g2[t + i * 256];
    }
    if (t < O_) s_lse_out[t] = d_lse_out[t];
    __syncthreads();

    const float logp = __uint_as_float(wlk.x) + w0v
                     - s_lse_out[o] - s_lse2[r2] - s_lse1[r1] - s_lse0[r0];

    const float xv = s_x[(s - s0) * D_ + cin];        // smem hit
    out[tid] = __sinf(__sinf(__sinf(xv)));            // [0, S, O] slice
    out[S_ * O_ + tid] = __expf(logp);                // [1, S, O] slice
}

extern "C" void kernel_launch(void* const* d_in, const int* in_sizes, int n_in,
                              void* d_out, int out_size)
{
    const float* x     = (const float*)d_in[0];
    const float* w0    = (const float*)d_in[1];
    const float* w1    = (const float*)d_in[2];
    const float* w2    = (const float*)d_in[3];
    const float* w_out = (const float*)d_in[4];
    const int*   c0    = (const int*)d_in[5];
    const int*   c1    = (const int*)d_in[6];
    const int*   c2    = (const int*)d_in[7];
    const int*   keys  = (const int*)d_in[8];
    float*       out   = (float*)d_out;

    const int blocksA = GATHER_BLOCKS + LSE_BLOCKS;
    lse_gather_kernel<<<blocksA, 256>>>(w0, w1, w2, w_out, c1, c2, keys);

    // PDL launch: B may start while A runs; its griddepcontrol.wait blocks
    // until A fully completes (memory visible). Graph capture records a
    // programmatic dependency edge.
    cudaLaunchConfig_t cfg = {};
    cfg.gridDim = dim3(GATHER_BLOCKS, 1, 1);
    cfg.blockDim = dim3(256, 1, 1);
    cfg.dynamicSmemBytes = 0;
    cfg.stream = 0;
    cudaLaunchAttribute attrs[1];
    attrs[0].id = cudaLaunchAttributeProgrammaticStreamSerialization;
    attrs[0].val.programmaticStreamSerializationAllowed = 1;
    cfg.attrs = attrs;
    cfg.numAttrs = 1;
    cudaLaunchKernelEx(&cfg, finalize_kernel, x, w0, c0, out);
}

// round 13
// speedup vs baseline: 1.2328x; 1.2328x over previous
#include <cuda_runtime.h>
#include <math.h>

#define S_ 8192
#define D_ 64
#define N_ 2048
#define O_ 8
#define GATHER_BLOCKS 256                 // walk: 256 x 256 thr = 65536 = S_*O_
#define LSE_BLOCKS (2 * N_ + O_ + N_ / 8) // 4360
#define B_BLOCKS 128                      // finalize: ONE wave (<=148 SMs)
#define HALF_ (S_ * O_ / 2)               // 32768: outputs per half

// ---- scratch (allocation-free rule: __device__ globals) ----
__device__ float d_lse0[N_];
__device__ float d_lse1[N_];
__device__ float d_lse2[N_];
__device__ float d_lse_out[O_];
__device__ uint4 d_walk[S_ * O_];   // {bits(w_out+w2+w1), r2, r1, r0}

// ---------------------------------------------------------------------------
// Kernel A: R7 structure, proven 5.67us. 3-round index walk (hides fully
// under the LSE MUFU floor) + row-wise logsumexp tables.
// ---------------------------------------------------------------------------
__global__ void __launch_bounds__(256) lse_gather_kernel(const float* __restrict__ w0,
                                                         const float* __restrict__ w1,
                                                         const float* __restrict__ w2,
                                                         const float* __restrict__ w_out,
                                                         const int* __restrict__ c1,
                                                         const int* __restrict__ c2,
                                                         const int* __restrict__ keys_out)
{
    __shared__ float smax[8];
    __shared__ float ssum[8];

    const int b = blockIdx.x;
    const int t = threadIdx.x;
    const int lane = t & 31;
    const int warp = t >> 5;

    if (b < GATHER_BLOCKS) {
        // ========== index walk: rounds 0-2 ==========
        const int tid = b * 256 + t;
        const int s = tid >> 3;          // / O_
        const int o = tid & 7;           // % O_

        const int r2 = keys_out[tid];                       // coalesced
        float logp = w_out[o * N_ + r2];

        const int r1 = c2[(size_t)s * N_ + r2];
        logp += w2[(size_t)r2 * N_ + r1];

        const int r0 = c1[(size_t)s * N_ + r1];
        logp += w1[(size_t)r1 * N_ + r0];

        d_walk[tid] = make_uint4(__float_as_uint(logp),
                                 (unsigned)r2, (unsigned)r1, (unsigned)r0);
        return;
    }

    const int b2 = b - GATHER_BLOCKS;
    if (b2 < 2 * N_ + O_) {
        // ================= wide rows: 2048 elements =================
        const float* row;
        float* dst;
        if (b2 < N_)          { row = w1    + (size_t)b2 * N_;           dst = &d_lse1[b2]; }
        else if (b2 < 2 * N_) { row = w2    + (size_t)(b2 - N_) * N_;    dst = &d_lse2[b2 - N_]; }
        else                  { row = w_out + (size_t)(b2 - 2*N_) * N_;  dst = &d_lse_out[b2 - 2*N_]; }

        const float4* row4 = (const float4*)row;
        float4 a = row4[t];
        float4 c = row4[t + 256];
        float v[8] = {a.x, a.y, a.z, a.w, c.x, c.y, c.z, c.w};

        float m = v[0];
        #pragma unroll
        for (int i = 1; i < 8; i++) m = fmaxf(m, v[i]);
        #pragma unroll
        for (int off = 16; off; off >>= 1) m = fmaxf(m, __shfl_xor_sync(0xffffffffu, m, off));
        if (lane == 0) smax[warp] = m;
        __syncthreads();
        float bm = smax[0];
        #pragma unroll
        for (int i = 1; i < 8; i++) bm = fmaxf(bm, smax[i]);

        float ss = 0.0f;
        #pragma unroll
        for (int i = 0; i < 8; i++) ss += __expf(v[i] - bm);
        #pragma unroll
        for (int off = 16; off; off >>= 1) ss += __shfl_xor_sync(0xffffffffu, ss, off);
        if (lane == 0) ssum[warp] = ss;
        __syncthreads();
        if (t == 0) {
            float tot = 0.0f;
            #pragma unroll
            for (int i = 0; i < 8; i++) tot += ssum[i];
            *dst = bm + __logf(tot);
        }
    } else {
        // ================= w0: 64-wide rows, one warp per row =================
        const int r = (b2 - (2 * N_ + O_)) * 8 + warp;
        const float* row = w0 + (size_t)r * D_;
        float v0 = row[lane];
        float v1 = row[lane + 32];
        float m = fmaxf(v0, v1);
        #pragma unroll
        for (int off = 16; off; off >>= 1) m = fmaxf(m, __shfl_xor_sync(0xffffffffu, m, off));
        float ss = __expf(v0 - m) + __expf(v1 - m);
        #pragma unroll
        for (int off = 16; off; off >>= 1) ss += __shfl_xor_sync(0xffffffffu, ss, off);
        if (lane == 0) d_lse0[r] = m + __logf(ss);
    }
}

// ---------------------------------------------------------------------------
// Kernel B, restructured (R13): 128 blocks (ONE wave), 2 outputs per thread
// (tid and tid+32768) -> MLP=2 on the lone c0 DRAM round; x is staged into
// smem by coalesced loads IN PARALLEL with the chains (x leaves the dependent
// path); tables staged once per block amortize over 2x outputs.
// ---------------------------------------------------------------------------
__global__ void __launch_bounds__(256) finalize_kernel(const float* __restrict__ x,
                                                       const float* __restrict__ w0,
                                                       const int* __restrict__ c0,
                                                       float* __restrict__ out)
{
    __shared__ float s_xa[32 * D_];     // 8 KB: samples [sA0, sA0+32)
    __shared__ float s_xb[32 * D_];     // 8 KB: samples [sA0+4096, +32)
    __shared__ float s_lse0[N_];
    __shared__ float s_lse1[N_];
    __shared__ float s_lse2[N_];
    __shared__ float s_lse_out[O_];

    const int t = threadIdx.x;
    const int tid0 = blockIdx.x * 256 + t;        // [0, 32768)
    const int tid1 = tid0 + HALF_;
    const int sA = tid0 >> 3;                     // sample for chain 0
    const int sB = sA + S_ / 2;                   // sample for chain 1 (+4096)
    const int o = tid0 & 7;
    const int sA0 = blockIdx.x * 32;              // block's first sample

    // ---- two independent dependent chains, issued back-to-back (MLP=2) ----
    const uint4 wa = d_walk[tid0];                // L2 (written by A)
    const uint4 wb = d_walk[tid1];
    const int cinA = c0[(size_t)sA * N_ + (int)wa.w];   // DRAM round (x2 overlapped)
    const int cinB = c0[(size_t)sB * N_ + (int)wb.w];
    const float w0vA = w0[(int)wa.w * D_ + cinA];       // L2 (A's LSE pass)
    const float w0vB = w0[(int)wb.w * D_ + cinB];

    // ---- independent staging, overlaps the chains ----
    // x rows for this block's 2x32 samples: coalesced float4 (16 KB total)
    const float4* xa4 = (const float4*)(x + (size_t)sA0 * D_);
    const float4* xb4 = (const float4*)(x + (size_t)(sA0 + S_ / 2) * D_);
    #pragma unroll
    for (int i = 0; i < 2; i++) {                 // 512 float4 each
        ((float4*)s_xa)[t + i * 256] = xa4[t + i * 256];
        ((float4*)s_xb)[t + i * 256] = xb4[t + i * 256];
    }
    // lse tables (24 KB, coalesced from L2)
    const float4* g0 = (const float4*)d_lse0;
    const float4* g1 = (const float4*)d_lse1;
    const float4* g2 = (const float4*)d_lse2;
    #pragma unroll
    for (int i = 0; i < N_ / 4 / 256; i++) {      // 2 iters
        ((float4*)s_lse0)[t + i * 256] = g0[t + i * 256];
        ((float4*)s_lse1)[t + i * 256] = g1[t + i * 256];
        ((float4*)s_lse2)[t + i * 256] = g2[t + i * 256];
    }
    if (t < O_) s_lse_out[t] = d_lse_out[t];
    __syncthreads();

    // ---- consume ----
    const float lo = s_lse_out[o];
    const float logpA = __uint_as_float(wa.x) + w0vA
                      - lo - s_lse2[wa.y] - s_lse1[wa.z] - s_lse0[wa.w];
    const float logpB = __uint_as_float(wb.x) + w0vB
                      - lo - s_lse2[wb.y] - s_lse1[wb.z] - s_lse0[wb.w];

    const float xvA = s_xa[(sA - sA0) * D_ + cinA];
    const float xvB = s_xb[(sA - sA0) * D_ + cinB];   // same local row index

    out[tid0] = __sinf(__sinf(__sinf(xvA)));          // [0, S, O] slice
    out[tid1] = __sinf(__sinf(__sinf(xvB)));
    out[S_ * O_ + tid0] = __expf(logpA);              // [1, S, O] slice
    out[S_ * O_ + tid1] = __expf(logpB);
}

extern "C" void kernel_launch(void* const* d_in, const int* in_sizes, int n_in,
                              void* d_out, int out_size)
{
    const float* x     = (const float*)d_in[0];
    const float* w0    = (const float*)d_in[1];
    const float* w1    = (const float*)d_in[2];
    const float* w2    = (const float*)d_in[3];
    const float* w_out = (const float*)d_in[4];
    const int*   c0    = (const int*)d_in[5];
    const int*   c1    = (const int*)d_in[6];
    const int*   c2    = (const int*)d_in[7];
    const int*   keys  = (const int*)d_in[8];
    float*       out   = (float*)d_out;

    const int blocksA = GATHER_BLOCKS + LSE_BLOCKS;
    lse_gather_kernel<<<blocksA, 256>>>(w0, w1, w2, w_out, c1, c2, keys);

    finalize_kernel<<<B_BLOCKS, 256>>>(x, w0, c0, out);
}

// round 14
// speedup vs baseline: 1.4264x; 1.1571x over previous
#include <cuda_runtime.h>
#include <math.h>

#define S_ 8192
#define D_ 64
#define N_ 2048
#define O_ 8
#define GATHER_BLOCKS 256                 // walk: 256 x 256 thr = 65536 = S_*O_
#define LSE_BLOCKS (2 * N_ + O_ + N_ / 8) // 4360
#define B_BLOCKS 128                      // finalize: ONE wave (<=148 SMs)
#define HALF_ (S_ * O_ / 2)               // 32768

// ---- scratch (allocation-free rule: __device__ globals) ----
__device__ float d_lse0[N_];
__device__ float d_lse1[N_];
__device__ float d_lse2[N_];
__device__ float d_lse_out[O_];
__device__ uint4 d_walk[S_ * O_];   // {bits(w_out+w2+w1+w0), r2, r1, (r0<<16)|cin}

// ---------------------------------------------------------------------------
// Kernel A: full 4-round walk (c0 + w0 piggybacked INTO the walk, isolated —
// unlike R10 there is no sy-precompute role perturbing the MUFU/HBM budget)
// + row-wise logsumexp tables. Walk threads have ~3us of slack before A's
// LSE floor (5.67us); the two extra dependent rounds (~900cyc) fit inside.
// ---------------------------------------------------------------------------
__global__ void __launch_bounds__(256) lse_gather_kernel(const float* __restrict__ w0,
                                                         const float* __restrict__ w1,
                                                         const float* __restrict__ w2,
                                                         const float* __restrict__ w_out,
                                                         const int* __restrict__ c0,
                                                         const int* __restrict__ c1,
                                                         const int* __restrict__ c2,
                                                         const int* __restrict__ keys_out)
{
    __shared__ float smax[8];
    __shared__ float ssum[8];

    const int b = blockIdx.x;
    const int t = threadIdx.x;
    const int lane = t & 31;
    const int warp = t >> 5;

    if (b < GATHER_BLOCKS) {
        // ========== full walk: rounds 0-3 + w0 (5 dependent rounds total) ==========
        const int tid = b * 256 + t;
        const int s = tid >> 3;          // / O_
        const int o = tid & 7;           // % O_

        const int r2 = keys_out[tid];                       // coalesced
        float logp = w_out[o * N_ + r2];

        const int r1 = c2[(size_t)s * N_ + r2];
        logp += w2[(size_t)r2 * N_ + r1];

        const int r0 = c1[(size_t)s * N_ + r1];
        logp += w1[(size_t)r1 * N_ + r0];

        const int cin = c0[(size_t)s * N_ + r0];            // piggyback round
        logp += w0[r0 * D_ + cin];                          // L2 (LSE pass warms w0)

        d_walk[tid] = make_uint4(__float_as_uint(logp),
                                 (unsigned)r2, (unsigned)r1,
                                 ((unsigned)r0 << 16) | (unsigned)cin);
        return;
    }

    const int b2 = b - GATHER_BLOCKS;
    if (b2 < 2 * N_ + O_) {
        // ================= wide rows: 2048 elements =================
        const float* row;
        float* dst;
        if (b2 < N_)          { row = w1    + (size_t)b2 * N_;           dst = &d_lse1[b2]; }
        else if (b2 < 2 * N_) { row = w2    + (size_t)(b2 - N_) * N_;    dst = &d_lse2[b2 - N_]; }
        else                  { row = w_out + (size_t)(b2 - 2*N_) * N_;  dst = &d_lse_out[b2 - 2*N_]; }

        const float4* row4 = (const float4*)row;
        float4 a = row4[t];
        float4 c = row4[t + 256];
        float v[8] = {a.x, a.y, a.z, a.w, c.x, c.y, c.z, c.w};

        float m = v[0];
        #pragma unroll
        for (int i = 1; i < 8; i++) m = fmaxf(m, v[i]);
        #pragma unroll
        for (int off = 16; off; off >>= 1) m = fmaxf(m, __shfl_xor_sync(0xffffffffu, m, off));
        if (lane == 0) smax[warp] = m;
        __syncthreads();
        float bm = smax[0];
        #pragma unroll
        for (int i = 1; i < 8; i++) bm = fmaxf(bm, smax[i]);

        float ss = 0.0f;
        #pragma unroll
        for (int i = 0; i < 8; i++) ss += __expf(v[i] - bm);
        #pragma unroll
        for (int off = 16; off; off >>= 1) ss += __shfl_xor_sync(0xffffffffu, ss, off);
        if (lane == 0) ssum[warp] = ss;
        __syncthreads();
        if (t == 0) {
            float tot = 0.0f;
            #pragma unroll
            for (int i = 0; i < 8; i++) tot += ssum[i];
            *dst = bm + __logf(tot);
        }
    } else {
        // ================= w0: 64-wide rows, one warp per row =================
        const int r = (b2 - (2 * N_ + O_)) * 8 + warp;
        const float* row = w0 + (size_t)r * D_;
        float v0 = row[lane];
        float v1 = row[lane + 32];
        float m = fmaxf(v0, v1);
        #pragma unroll
        for (int off = 16; off; off >>= 1) m = fmaxf(m, __shfl_xor_sync(0xffffffffu, m, off));
        float ss = __expf(v0 - m) + __expf(v1 - m);
        #pragma unroll
        for (int off = 16; off; off >>= 1) ss += __shfl_xor_sync(0xffffffffu, ss, off);
        if (lane == 0) d_lse0[r] = m + __logf(ss);
    }
}

// ---------------------------------------------------------------------------
// Kernel B: ZERO divergent DRAM work. One wave (128 blocks), 2 outputs per
// thread. Coalesced d_walk read (logp already includes w0); x rows staged
// into smem (coalesced); tables staged into smem; divergent accesses are all
// LDS. This is R6's proven ~5us B plus cheap coalesced staging.
// ---------------------------------------------------------------------------
__global__ void __launch_bounds__(256) finalize_kernel(const float* __restrict__ x,
                                                       float* __restrict__ out)
{
    __shared__ float s_xa[32 * D_];     // samples [sA0, sA0+32)
    __shared__ float s_xb[32 * D_];     // samples [sA0+4096, +32)
    __shared__ float s_lse0[N_];
    __shared__ float s_lse1[N_];
    __shared__ float s_lse2[N_];
    __shared__ float s_lse_out[O_];

    const int t = threadIdx.x;
    const int tid0 = blockIdx.x * 256 + t;        // [0, 32768)
    const int tid1 = tid0 + HALF_;
    const int sA = tid0 >> 3;
    const int o = tid0 & 7;
    const int sA0 = blockIdx.x * 32;

    // coalesced walk reads (L2, written by A)
    const uint4 wa = d_walk[tid0];
    const uint4 wb = d_walk[tid1];

    // ---- staging: all coalesced, overlaps nothing dependent ----
    const float4* xa4 = (const float4*)(x + (size_t)sA0 * D_);
    const float4* xb4 = (const float4*)(x + (size_t)(sA0 + S_ / 2) * D_);
    #pragma unroll
    for (int i = 0; i < 2; i++) {                 // 512 float4 each
        ((float4*)s_xa)[t + i * 256] = xa4[t + i * 256];
        ((float4*)s_xb)[t + i * 256] = xb4[t + i * 256];
    }
    const float4* g0 = (const float4*)d_lse0;
    const float4* g1 = (const float4*)d_lse1;
    const float4* g2 = (const float4*)d_lse2;
    #pragma unroll
    for (int i = 0; i < N_ / 4 / 256; i++) {      // 2 iters
        ((float4*)s_lse0)[t + i * 256] = g0[t + i * 256];
        ((float4*)s_lse1)[t + i * 256] = g1[t + i * 256];
        ((float4*)s_lse2)[t + i * 256] = g2[t + i * 256];
    }
    if (t < O_) s_lse_out[t] = d_lse_out[t];
    __syncthreads();

    // ---- consume: divergent accesses are all LDS ----
    const int r0A = (int)(wa.w >> 16), cinA = (int)(wa.w & 0xFFFFu);
    const int r0B = (int)(wb.w >> 16), cinB = (int)(wb.w & 0xFFFFu);
    const float lo = s_lse_out[o];

    const float logpA = __uint_as_float(wa.x)
                      - lo - s_lse2[wa.y] - s_lse1[wa.z] - s_lse0[r0A];
    const float logpB = __uint_as_float(wb.x)
                      - lo - s_lse2[wb.y] - s_lse1[wb.z] - s_lse0[r0B];

    const int lrow = sA - sA0;
    const float xvA = s_xa[lrow * D_ + cinA];
    const float xvB = s_xb[lrow * D_ + cinB];

    out[tid0] = __sinf(__sinf(__sinf(xvA)));          // [0, S, O] slice
    out[tid1] = __sinf(__sinf(__sinf(xvB)));
    out[S_ * O_ + tid0] = __expf(logpA);              // [1, S, O] slice
    out[S_ * O_ + tid1] = __expf(logpB);
}

extern "C" void kernel_launch(void* const* d_in, const int* in_sizes, int n_in,
                              void* d_out, int out_size)
{
    const float* x     = (const float*)d_in[0];
    const float* w0    = (const float*)d_in[1];
    const float* w1    = (const float*)d_in[2];
    const float* w2    = (const float*)d_in[3];
    const float* w_out = (const float*)d_in[4];
    const int*   c0    = (const int*)d_in[5];
    const int*   c1    = (const int*)d_in[6];
    const int*   c2    = (const int*)d_in[7];
    const int*   keys  = (const int*)d_in[8];
    float*       out   = (float*)d_out;

    const int blocksA = GATHER_BLOCKS + LSE_BLOCKS;
    lse_gather_kernel<<<blocksA, 256>>>(w0, w1, w2, w_out, c0, c1, c2, keys);

    finalize_kernel<<<B_BLOCKS, 256>>>(x, out);
}